// round 10
// baseline (speedup 1.0000x reference)
#include <cuda_runtime.h>
#include <cstdint>

// Problem constants (fixed by setup_inputs)
#define BATCH   8
#define LEN     4096
#define ROWS    (BATCH * LEN)      // 32768
#define NST     256                // state/input/output size
#define KHALF   128                // number of 2x2 blocks
#define LC      64                 // scan chunk length
#define CHUNKS  (ROWS / LC)        // 512
#define CPB     (LEN / LC)         // 64 chunks per batch sequence

// Scratch (device globals: no allocation allowed)
__device__ float g_x1[ROWS * NST];     // u @ B
__device__ float g_x [ROWS * NST];     // recurrence output
__device__ float g_s [CHUNKS * NST];   // per-chunk local scan results (complex, interleaved)
__device__ float g_in[CHUNKS * NST];   // per-chunk incoming states

// ---------------------------------------------------------------------------
// tf32 tensor-core GEMM:  D[M,256] = A[M,256] @ B[256,256], all row-major f32
// Block tile 64x256 (full N -> A read once), BK=16, 4 warps, warp tile 64x64.
// ---------------------------------------------------------------------------

__device__ __forceinline__ uint32_t f2tf(float f) {
    uint32_t r;
    asm("cvt.rna.tf32.f32 %0, %1;" : "=r"(r) : "f"(f));
    return r;
}

__device__ __forceinline__ void mma_tf32(float* d, const uint32_t* a, const uint32_t* b) {
    asm volatile(
        "mma.sync.aligned.m16n8k8.row.col.f32.tf32.tf32.f32 "
        "{%0,%1,%2,%3}, {%4,%5,%6,%7}, {%8,%9}, {%0,%1,%2,%3};\n"
        : "+f"(d[0]), "+f"(d[1]), "+f"(d[2]), "+f"(d[3])
        : "r"(a[0]), "r"(a[1]), "r"(a[2]), "r"(a[3]), "r"(b[0]), "r"(b[1]));
}

__device__ __forceinline__ void cp16(uint32_t smem, const void* gmem) {
    asm volatile("cp.async.ca.shared.global [%0], [%1], 16;\n" :: "r"(smem), "l"(gmem));
}

// PH=0: Ain = u (param), Dout = g_x1 (internal)
// PH=1: Ain = g_x (internal), Dout = y (param)
template <int PH>
__global__ void __launch_bounds__(128) gemm_k(const float* __restrict__ Ain,
                                              const float* __restrict__ Bin,
                                              float* __restrict__ Dout)
{
    const float* __restrict__ Ag = (PH == 0) ? Ain : g_x;
    float* __restrict__ Dg       = (PH == 0) ? g_x1 : Dout;

    __shared__ float As[2][64][20];    // pad 4: conflict-free A fragment LDS
    __shared__ float Bs[2][16][264];   // pad 8: conflict-free B fragment LDS

    const int tid  = threadIdx.x;
    const int warp = tid >> 5;
    const int lane = tid & 31;
    const int g = lane >> 2, t = lane & 3;
    const long mbase = (long)blockIdx.x * 64;

    auto loadTile = [&](int k0, int buf) {
        // A tile: 64 rows x 16 cols  (256 x 16B)
        #pragma unroll
        for (int p = 0; p < 2; ++p) {
            int ch = tid + p * 128;
            int r = ch >> 2, c4 = (ch & 3) * 4;
            cp16((uint32_t)__cvta_generic_to_shared(&As[buf][r][c4]),
                 Ag + (mbase + r) * NST + k0 + c4);
        }
        // B tile: 16 rows x 256 cols (1024 x 16B)
        #pragma unroll
        for (int p = 0; p < 8; ++p) {
            int ch = tid + p * 128;
            int r = ch >> 6, c = (ch & 63) * 4;
            cp16((uint32_t)__cvta_generic_to_shared(&Bs[buf][r][c]),
                 Bin + (k0 + r) * NST + c);
        }
        asm volatile("cp.async.commit_group;\n");
    };

    float acc[4][8][4];
    #pragma unroll
    for (int i = 0; i < 4; ++i)
        #pragma unroll
        for (int j = 0; j < 8; ++j)
            #pragma unroll
            for (int q = 0; q < 4; ++q) acc[i][j][q] = 0.f;

    loadTile(0, 0);

    for (int it = 0; it < 16; ++it) {
        if (it + 1 < 16) {
            loadTile((it + 1) * 16, (it + 1) & 1);
            asm volatile("cp.async.wait_group 1;\n");
        } else {
            asm volatile("cp.async.wait_group 0;\n");
        }
        __syncthreads();

        const int buf = it & 1;
        const int nb0 = warp * 64;
        #pragma unroll
        for (int kk = 0; kk < 16; kk += 8) {
            uint32_t af[4][4], bf[8][2];
            #pragma unroll
            for (int i = 0; i < 4; ++i) {
                af[i][0] = f2tf(As[buf][i * 16 + g    ][kk + t    ]);
                af[i][1] = f2tf(As[buf][i * 16 + g + 8][kk + t    ]);
                af[i][2] = f2tf(As[buf][i * 16 + g    ][kk + t + 4]);
                af[i][3] = f2tf(As[buf][i * 16 + g + 8][kk + t + 4]);
            }
            #pragma unroll
            for (int j = 0; j < 8; ++j) {
                bf[j][0] = f2tf(Bs[buf][kk + t    ][nb0 + j * 8 + g]);
                bf[j][1] = f2tf(Bs[buf][kk + t + 4][nb0 + j * 8 + g]);
            }
            #pragma unroll
            for (int i = 0; i < 4; ++i)
                #pragma unroll
                for (int j = 0; j < 8; ++j)
                    mma_tf32(acc[i][j], af[i], bf[j]);
        }
        __syncthreads();
    }

    // Epilogue: D fragment c0,c1 at (row g, col 2t/2t+1); c2,c3 at row g+8
    #pragma unroll
    for (int i = 0; i < 4; ++i) {
        long r0 = mbase + i * 16 + g;
        #pragma unroll
        for (int j = 0; j < 8; ++j) {
            int cn = warp * 64 + j * 8 + 2 * t;
            *(float2*)&Dg[r0 * NST + cn]       = make_float2(acc[i][j][0], acc[i][j][1]);
            *(float2*)&Dg[(r0 + 8) * NST + cn] = make_float2(acc[i][j][2], acc[i][j][3]);
        }
    }
}

// ---------------------------------------------------------------------------
// Scan phase A: per-chunk local recurrence with zero initial state.
// One block per chunk (512), one thread per k (128). Coalesced float2 reads.
//   s_c = result of z <- z*w + p over the chunk, z init 0
// ---------------------------------------------------------------------------
__global__ void __launch_bounds__(128) scan_local(const float* __restrict__ Arot)
{
    const int cid = blockIdx.x;
    const int k = threadIdx.x;
    const float wc = Arot[k * 4 + 0];
    const float ws = Arot[k * 4 + 1];
    const float2* p = (const float2*)(g_x1 + (size_t)cid * LC * NST) + k;

    float zr = 0.f, zi = 0.f;
    #pragma unroll 8
    for (int tt = 0; tt < LC; ++tt) {
        float2 v = p[(size_t)tt * (NST / 2)];
        float nr = fmaf(zr, wc, fmaf(-zi, ws, v.x));
        float ni = fmaf(zr, ws, fmaf( zi, wc, v.y));
        zr = nr; zi = ni;
    }
    ((float2*)g_s)[cid * KHALF + k] = make_float2(zr, zi);
}

// ---------------------------------------------------------------------------
// Scan phase B: carry propagation across chunks per (b,k); emits new_state.
//   in_0 = x0;  in_{c+1} = in_c * w^LC + s_c;  new_state = in_{CPB}
// w^LC computed by 6 complex squarings (LC=64) — avoids sin(t*theta) blowup.
// ---------------------------------------------------------------------------
__global__ void __launch_bounds__(1024) scan_carry(const float* __restrict__ Arot,
                                                   const float* __restrict__ x0,
                                                   float* __restrict__ tail,
                                                   int write_tail)
{
    const int tid = threadIdx.x;           // 0..1023
    const int b = tid >> 7, k = tid & 127;

    float Wr = Arot[k * 4 + 0];
    float Wi = Arot[k * 4 + 1];
    #pragma unroll
    for (int i = 0; i < 6; ++i) {          // w -> w^2 -> ... -> w^64
        float nr = Wr * Wr - Wi * Wi;
        float ni = 2.f * Wr * Wi;
        Wr = nr; Wi = ni;
    }

    float2 z = ((const float2*)x0)[b * KHALF + k];
    float zr = z.x, zi = z.y;
    for (int c = 0; c < CPB; ++c) {
        const int cid = b * CPB + c;
        ((float2*)g_in)[cid * KHALF + k] = make_float2(zr, zi);
        float2 s = ((const float2*)g_s)[cid * KHALF + k];
        float nr = fmaf(zr, Wr, fmaf(-zi, Wi, s.x));
        float ni = fmaf(zr, Wi, fmaf( zi, Wr, s.y));
        zr = nr; zi = ni;
    }
    if (write_tail)
        ((float2*)tail)[b * KHALF + k] = make_float2(zr, zi);
}

// ---------------------------------------------------------------------------
// Scan phase C: replay each chunk with the correct incoming state, write x.
// ---------------------------------------------------------------------------
__global__ void __launch_bounds__(128) scan_apply(const float* __restrict__ Arot)
{
    const int cid = blockIdx.x;
    const int k = threadIdx.x;
    const float wc = Arot[k * 4 + 0];
    const float ws = Arot[k * 4 + 1];
    const float2* p = (const float2*)(g_x1 + (size_t)cid * LC * NST) + k;
    float2*       q = (float2*)      (g_x  + (size_t)cid * LC * NST) + k;

    float2 z0 = ((const float2*)g_in)[cid * KHALF + k];
    float zr = z0.x, zi = z0.y;
    #pragma unroll 8
    for (int tt = 0; tt < LC; ++tt) {
        float2 v = p[(size_t)tt * (NST / 2)];
        float nr = fmaf(zr, wc, fmaf(-zi, ws, v.x));
        float ni = fmaf(zr, ws, fmaf( zi, wc, v.y));
        zr = nr; zi = ni;
        q[(size_t)tt * (NST / 2)] = make_float2(zr, zi);
    }
}

// ---------------------------------------------------------------------------
// Launch: gemm1 -> scan A -> scan B -> scan C -> gemm2
// Output: y (8*4096*256 f32) then new_state (8*128*2 f32), concatenated.
// ---------------------------------------------------------------------------
extern "C" void kernel_launch(void* const* d_in, const int* in_sizes, int n_in,
                              void* d_out, int out_size)
{
    const float* u  = (const float*)d_in[0];
    const float* x0 = (const float*)d_in[1];
    const float* A  = (const float*)d_in[2];
    const float* B  = (const float*)d_in[3];
    const float* C  = (const float*)d_in[4];
    float* out = (float*)d_out;

    const int YSZ = ROWS * NST;                       // 8388608
    const int TSZ = BATCH * KHALF * 2;                // 2048
    const int wt = (out_size >= YSZ + TSZ) ? 1 : 0;
    float* tail = out + YSZ;

    gemm_k<0><<<ROWS / 64, 128>>>(u, B, out);         // x1 = u @ B   (writes g_x1)
    scan_local<<<CHUNKS, 128>>>(A);                   // per-chunk local scans
    scan_carry<<<1, 1024>>>(A, x0, tail, wt);         // carries + new_state
    scan_apply<<<CHUNKS, 128>>>(A);                   // x (writes g_x)
    gemm_k<1><<<ROWS / 64, 128>>>(u, C, out);         // y = x @ C    (reads g_x)
}

// round 11
// speedup vs baseline: 1.0003x; 1.0003x over previous
#include <cuda_runtime.h>
#include <cstdint>

// Problem constants (fixed by setup_inputs)
#define BATCH   8
#define LEN     4096
#define ROWS    (BATCH * LEN)      // 32768
#define NST     256                // state/input/output size
#define KHALF   128                // number of 2x2 blocks
#define LC      64                 // scan chunk length
#define CHUNKS  (ROWS / LC)        // 512
#define CPB     (LEN / LC)         // 64 chunks per batch sequence

// Scratch (device globals: no allocation allowed)
__device__ float g_x1[ROWS * NST];     // u @ B
__device__ float g_x [ROWS * NST];     // recurrence output
__device__ float g_s [CHUNKS * NST];   // per-chunk local scan results (complex, interleaved)
__device__ float g_in[CHUNKS * NST];   // per-chunk incoming states

// ---------------------------------------------------------------------------
// tf32 tensor-core GEMM:  D[M,256] = A[M,256] @ B[256,256], all row-major f32
// Block tile 64x256 (full N -> A read once), BK=16, 4 warps, warp tile 64x64.
// ---------------------------------------------------------------------------

__device__ __forceinline__ uint32_t f2tf(float f) {
    uint32_t r;
    asm("cvt.rna.tf32.f32 %0, %1;" : "=r"(r) : "f"(f));
    return r;
}

__device__ __forceinline__ void mma_tf32(float* d, const uint32_t* a, const uint32_t* b) {
    asm volatile(
        "mma.sync.aligned.m16n8k8.row.col.f32.tf32.tf32.f32 "
        "{%0,%1,%2,%3}, {%4,%5,%6,%7}, {%8,%9}, {%0,%1,%2,%3};\n"
        : "+f"(d[0]), "+f"(d[1]), "+f"(d[2]), "+f"(d[3])
        : "r"(a[0]), "r"(a[1]), "r"(a[2]), "r"(a[3]), "r"(b[0]), "r"(b[1]));
}

__device__ __forceinline__ void cp16(uint32_t smem, const void* gmem) {
    asm volatile("cp.async.ca.shared.global [%0], [%1], 16;\n" :: "r"(smem), "l"(gmem));
}

// PH=0: Ain = u (param), Dout = g_x1 (internal)
// PH=1: Ain = g_x (internal), Dout = y (param)
template <int PH>
__global__ void __launch_bounds__(128) gemm_k(const float* __restrict__ Ain,
                                              const float* __restrict__ Bin,
                                              float* __restrict__ Dout)
{
    const float* __restrict__ Ag = (PH == 0) ? Ain : g_x;
    float* __restrict__ Dg       = (PH == 0) ? g_x1 : Dout;

    __shared__ float As[2][64][20];    // pad 4: conflict-free A fragment LDS
    __shared__ float Bs[2][16][264];   // pad 8: conflict-free B fragment LDS

    const int tid  = threadIdx.x;
    const int warp = tid >> 5;
    const int lane = tid & 31;
    const int g = lane >> 2, t = lane & 3;
    const long mbase = (long)blockIdx.x * 64;

    auto loadTile = [&](int k0, int buf) {
        // A tile: 64 rows x 16 cols  (256 x 16B)
        #pragma unroll
        for (int p = 0; p < 2; ++p) {
            int ch = tid + p * 128;
            int r = ch >> 2, c4 = (ch & 3) * 4;
            cp16((uint32_t)__cvta_generic_to_shared(&As[buf][r][c4]),
                 Ag + (mbase + r) * NST + k0 + c4);
        }
        // B tile: 16 rows x 256 cols (1024 x 16B)
        #pragma unroll
        for (int p = 0; p < 8; ++p) {
            int ch = tid + p * 128;
            int r = ch >> 6, c = (ch & 63) * 4;
            cp16((uint32_t)__cvta_generic_to_shared(&Bs[buf][r][c]),
                 Bin + (k0 + r) * NST + c);
        }
        asm volatile("cp.async.commit_group;\n");
    };

    float acc[4][8][4];
    #pragma unroll
    for (int i = 0; i < 4; ++i)
        #pragma unroll
        for (int j = 0; j < 8; ++j)
            #pragma unroll
            for (int q = 0; q < 4; ++q) acc[i][j][q] = 0.f;

    loadTile(0, 0);

    for (int it = 0; it < 16; ++it) {
        if (it + 1 < 16) {
            loadTile((it + 1) * 16, (it + 1) & 1);
            asm volatile("cp.async.wait_group 1;\n");
        } else {
            asm volatile("cp.async.wait_group 0;\n");
        }
        __syncthreads();

        const int buf = it & 1;
        const int nb0 = warp * 64;
        #pragma unroll
        for (int kk = 0; kk < 16; kk += 8) {
            uint32_t af[4][4], bf[8][2];
            #pragma unroll
            for (int i = 0; i < 4; ++i) {
                af[i][0] = f2tf(As[buf][i * 16 + g    ][kk + t    ]);
                af[i][1] = f2tf(As[buf][i * 16 + g + 8][kk + t    ]);
                af[i][2] = f2tf(As[buf][i * 16 + g    ][kk + t + 4]);
                af[i][3] = f2tf(As[buf][i * 16 + g + 8][kk + t + 4]);
            }
            #pragma unroll
            for (int j = 0; j < 8; ++j) {
                bf[j][0] = f2tf(Bs[buf][kk + t    ][nb0 + j * 8 + g]);
                bf[j][1] = f2tf(Bs[buf][kk + t + 4][nb0 + j * 8 + g]);
            }
            #pragma unroll
            for (int i = 0; i < 4; ++i)
                #pragma unroll
                for (int j = 0; j < 8; ++j)
                    mma_tf32(acc[i][j], af[i], bf[j]);
        }
        __syncthreads();
    }

    // Epilogue: D fragment c0,c1 at (row g, col 2t/2t+1); c2,c3 at row g+8
    #pragma unroll
    for (int i = 0; i < 4; ++i) {
        long r0 = mbase + i * 16 + g;
        #pragma unroll
        for (int j = 0; j < 8; ++j) {
            int cn = warp * 64 + j * 8 + 2 * t;
            *(float2*)&Dg[r0 * NST + cn]       = make_float2(acc[i][j][0], acc[i][j][1]);
            *(float2*)&Dg[(r0 + 8) * NST + cn] = make_float2(acc[i][j][2], acc[i][j][3]);
        }
    }
}

// ---------------------------------------------------------------------------
// Scan phase A: per-chunk local recurrence with zero initial state.
// One block per chunk (512), one thread per k (128). Coalesced float2 reads.
//   s_c = result of z <- z*w + p over the chunk, z init 0
// ---------------------------------------------------------------------------
__global__ void __launch_bounds__(128) scan_local(const float* __restrict__ Arot)
{
    const int cid = blockIdx.x;
    const int k = threadIdx.x;
    const float wc = Arot[k * 4 + 0];
    const float ws = Arot[k * 4 + 1];
    const float2* p = (const float2*)(g_x1 + (size_t)cid * LC * NST) + k;

    float zr = 0.f, zi = 0.f;
    #pragma unroll 8
    for (int tt = 0; tt < LC; ++tt) {
        float2 v = p[(size_t)tt * (NST / 2)];
        float nr = fmaf(zr, wc, fmaf(-zi, ws, v.x));
        float ni = fmaf(zr, ws, fmaf( zi, wc, v.y));
        zr = nr; zi = ni;
    }
    ((float2*)g_s)[cid * KHALF + k] = make_float2(zr, zi);
}

// ---------------------------------------------------------------------------
// Scan phase B: carry propagation across chunks per (b,k); emits new_state.
//   in_0 = x0;  in_{c+1} = in_c * w^LC + s_c;  new_state = in_{CPB}
// w^LC computed by 6 complex squarings (LC=64) — avoids sin(t*theta) blowup.
// ---------------------------------------------------------------------------
__global__ void __launch_bounds__(1024) scan_carry(const float* __restrict__ Arot,
                                                   const float* __restrict__ x0,
                                                   float* __restrict__ tail,
                                                   int write_tail)
{
    const int tid = threadIdx.x;           // 0..1023
    const int b = tid >> 7, k = tid & 127;

    float Wr = Arot[k * 4 + 0];
    float Wi = Arot[k * 4 + 1];
    #pragma unroll
    for (int i = 0; i < 6; ++i) {          // w -> w^2 -> ... -> w^64
        float nr = Wr * Wr - Wi * Wi;
        float ni = 2.f * Wr * Wi;
        Wr = nr; Wi = ni;
    }

    float2 z = ((const float2*)x0)[b * KHALF + k];
    float zr = z.x, zi = z.y;
    for (int c = 0; c < CPB; ++c) {
        const int cid = b * CPB + c;
        ((float2*)g_in)[cid * KHALF + k] = make_float2(zr, zi);
        float2 s = ((const float2*)g_s)[cid * KHALF + k];
        float nr = fmaf(zr, Wr, fmaf(-zi, Wi, s.x));
        float ni = fmaf(zr, Wi, fmaf( zi, Wr, s.y));
        zr = nr; zi = ni;
    }
    if (write_tail)
        ((float2*)tail)[b * KHALF + k] = make_float2(zr, zi);
}

// ---------------------------------------------------------------------------
// Scan phase C: replay each chunk with the correct incoming state, write x.
// ---------------------------------------------------------------------------
__global__ void __launch_bounds__(128) scan_apply(const float* __restrict__ Arot)
{
    const int cid = blockIdx.x;
    const int k = threadIdx.x;
    const float wc = Arot[k * 4 + 0];
    const float ws = Arot[k * 4 + 1];
    const float2* p = (const float2*)(g_x1 + (size_t)cid * LC * NST) + k;
    float2*       q = (float2*)      (g_x  + (size_t)cid * LC * NST) + k;

    float2 z0 = ((const float2*)g_in)[cid * KHALF + k];
    float zr = z0.x, zi = z0.y;
    #pragma unroll 8
    for (int tt = 0; tt < LC; ++tt) {
        float2 v = p[(size_t)tt * (NST / 2)];
        float nr = fmaf(zr, wc, fmaf(-zi, ws, v.x));
        float ni = fmaf(zr, ws, fmaf( zi, wc, v.y));
        zr = nr; zi = ni;
        q[(size_t)tt * (NST / 2)] = make_float2(zr, zi);
    }
}

// ---------------------------------------------------------------------------
// Launch: gemm1 -> scan A -> scan B -> scan C -> gemm2
// Output: y (8*4096*256 f32) then new_state (8*128*2 f32), concatenated.
// ---------------------------------------------------------------------------
extern "C" void kernel_launch(void* const* d_in, const int* in_sizes, int n_in,
                              void* d_out, int out_size)
{
    const float* u  = (const float*)d_in[0];
    const float* x0 = (const float*)d_in[1];
    const float* A  = (const float*)d_in[2];
    const float* B  = (const float*)d_in[3];
    const float* C  = (const float*)d_in[4];
    float* out = (float*)d_out;

    const int YSZ = ROWS * NST;                       // 8388608
    const int TSZ = BATCH * KHALF * 2;                // 2048
    const int wt = (out_size >= YSZ + TSZ) ? 1 : 0;
    float* tail = out + YSZ;

    gemm_k<0><<<ROWS / 64, 128>>>(u, B, out);         // x1 = u @ B   (writes g_x1)
    scan_local<<<CHUNKS, 128>>>(A);                   // per-chunk local scans
    scan_carry<<<1, 1024>>>(A, x0, tail, wt);         // carries + new_state
    scan_apply<<<CHUNKS, 128>>>(A);                   // x (writes g_x)
    gemm_k<1><<<ROWS / 64, 128>>>(u, C, out);         // y = x @ C    (reads g_x)
}

// round 12
// speedup vs baseline: 1.0005x; 1.0003x over previous
#include <cuda_runtime.h>
#include <cstdint>

// Problem constants (fixed by setup_inputs)
#define BATCH   8
#define LEN     4096
#define ROWS    (BATCH * LEN)      // 32768
#define NST     256                // state/input/output size
#define KHALF   128                // number of 2x2 blocks
#define LC      64                 // scan chunk length
#define CHUNKS  (ROWS / LC)        // 512
#define CPB     (LEN / LC)         // 64 chunks per batch sequence

// Scratch (device globals: no allocation allowed)
__device__ float g_x1[ROWS * NST];     // u @ B
__device__ float g_x [ROWS * NST];     // recurrence output
__device__ float g_s [CHUNKS * NST];   // per-chunk local scan results (complex, interleaved)
__device__ float g_in[CHUNKS * NST];   // per-chunk incoming states

// ---------------------------------------------------------------------------
// tf32 tensor-core GEMM:  D[M,256] = A[M,256] @ B[256,256], all row-major f32
// Block tile 64x256 (full N -> A read once), BK=16, 4 warps, warp tile 64x64.
// ---------------------------------------------------------------------------

__device__ __forceinline__ uint32_t f2tf(float f) {
    uint32_t r;
    asm("cvt.rna.tf32.f32 %0, %1;" : "=r"(r) : "f"(f));
    return r;
}

__device__ __forceinline__ void mma_tf32(float* d, const uint32_t* a, const uint32_t* b) {
    asm volatile(
        "mma.sync.aligned.m16n8k8.row.col.f32.tf32.tf32.f32 "
        "{%0,%1,%2,%3}, {%4,%5,%6,%7}, {%8,%9}, {%0,%1,%2,%3};\n"
        : "+f"(d[0]), "+f"(d[1]), "+f"(d[2]), "+f"(d[3])
        : "r"(a[0]), "r"(a[1]), "r"(a[2]), "r"(a[3]), "r"(b[0]), "r"(b[1]));
}

__device__ __forceinline__ void cp16(uint32_t smem, const void* gmem) {
    asm volatile("cp.async.ca.shared.global [%0], [%1], 16;\n" :: "r"(smem), "l"(gmem));
}

// PH=0: Ain = u (param), Dout = g_x1 (internal)
// PH=1: Ain = g_x (internal), Dout = y (param)
template <int PH>
__global__ void __launch_bounds__(128) gemm_k(const float* __restrict__ Ain,
                                              const float* __restrict__ Bin,
                                              float* __restrict__ Dout)
{
    const float* __restrict__ Ag = (PH == 0) ? Ain : g_x;
    float* __restrict__ Dg       = (PH == 0) ? g_x1 : Dout;

    __shared__ float As[2][64][20];    // pad 4: conflict-free A fragment LDS
    __shared__ float Bs[2][16][264];   // pad 8: conflict-free B fragment LDS

    const int tid  = threadIdx.x;
    const int warp = tid >> 5;
    const int lane = tid & 31;
    const int g = lane >> 2, t = lane & 3;
    const long mbase = (long)blockIdx.x * 64;

    auto loadTile = [&](int k0, int buf) {
        // A tile: 64 rows x 16 cols  (256 x 16B)
        #pragma unroll
        for (int p = 0; p < 2; ++p) {
            int ch = tid + p * 128;
            int r = ch >> 2, c4 = (ch & 3) * 4;
            cp16((uint32_t)__cvta_generic_to_shared(&As[buf][r][c4]),
                 Ag + (mbase + r) * NST + k0 + c4);
        }
        // B tile: 16 rows x 256 cols (1024 x 16B)
        #pragma unroll
        for (int p = 0; p < 8; ++p) {
            int ch = tid + p * 128;
            int r = ch >> 6, c = (ch & 63) * 4;
            cp16((uint32_t)__cvta_generic_to_shared(&Bs[buf][r][c]),
                 Bin + (k0 + r) * NST + c);
        }
        asm volatile("cp.async.commit_group;\n");
    };

    float acc[4][8][4];
    #pragma unroll
    for (int i = 0; i < 4; ++i)
        #pragma unroll
        for (int j = 0; j < 8; ++j)
            #pragma unroll
            for (int q = 0; q < 4; ++q) acc[i][j][q] = 0.f;

    loadTile(0, 0);

    for (int it = 0; it < 16; ++it) {
        if (it + 1 < 16) {
            loadTile((it + 1) * 16, (it + 1) & 1);
            asm volatile("cp.async.wait_group 1;\n");
        } else {
            asm volatile("cp.async.wait_group 0;\n");
        }
        __syncthreads();

        const int buf = it & 1;
        const int nb0 = warp * 64;
        #pragma unroll
        for (int kk = 0; kk < 16; kk += 8) {
            uint32_t af[4][4], bf[8][2];
            #pragma unroll
            for (int i = 0; i < 4; ++i) {
                af[i][0] = f2tf(As[buf][i * 16 + g    ][kk + t    ]);
                af[i][1] = f2tf(As[buf][i * 16 + g + 8][kk + t    ]);
                af[i][2] = f2tf(As[buf][i * 16 + g    ][kk + t + 4]);
                af[i][3] = f2tf(As[buf][i * 16 + g + 8][kk + t + 4]);
            }
            #pragma unroll
            for (int j = 0; j < 8; ++j) {
                bf[j][0] = f2tf(Bs[buf][kk + t    ][nb0 + j * 8 + g]);
                bf[j][1] = f2tf(Bs[buf][kk + t + 4][nb0 + j * 8 + g]);
            }
            #pragma unroll
            for (int i = 0; i < 4; ++i)
                #pragma unroll
                for (int j = 0; j < 8; ++j)
                    mma_tf32(acc[i][j], af[i], bf[j]);
        }
        __syncthreads();
    }

    // Epilogue: D fragment c0,c1 at (row g, col 2t/2t+1); c2,c3 at row g+8
    #pragma unroll
    for (int i = 0; i < 4; ++i) {
        long r0 = mbase + i * 16 + g;
        #pragma unroll
        for (int j = 0; j < 8; ++j) {
            int cn = warp * 64 + j * 8 + 2 * t;
            *(float2*)&Dg[r0 * NST + cn]       = make_float2(acc[i][j][0], acc[i][j][1]);
            *(float2*)&Dg[(r0 + 8) * NST + cn] = make_float2(acc[i][j][2], acc[i][j][3]);
        }
    }
}

// ---------------------------------------------------------------------------
// Scan phase A: per-chunk local recurrence with zero initial state.
// One block per chunk (512), one thread per k (128). Coalesced float2 reads.
//   s_c = result of z <- z*w + p over the chunk, z init 0
// ---------------------------------------------------------------------------
__global__ void __launch_bounds__(128) scan_local(const float* __restrict__ Arot)
{
    const int cid = blockIdx.x;
    const int k = threadIdx.x;
    const float wc = Arot[k * 4 + 0];
    const float ws = Arot[k * 4 + 1];
    const float2* p = (const float2*)(g_x1 + (size_t)cid * LC * NST) + k;

    float zr = 0.f, zi = 0.f;
    #pragma unroll 8
    for (int tt = 0; tt < LC; ++tt) {
        float2 v = p[(size_t)tt * (NST / 2)];
        float nr = fmaf(zr, wc, fmaf(-zi, ws, v.x));
        float ni = fmaf(zr, ws, fmaf( zi, wc, v.y));
        zr = nr; zi = ni;
    }
    ((float2*)g_s)[cid * KHALF + k] = make_float2(zr, zi);
}

// ---------------------------------------------------------------------------
// Scan phase B: carry propagation across chunks per (b,k); emits new_state.
//   in_0 = x0;  in_{c+1} = in_c * w^LC + s_c;  new_state = in_{CPB}
// w^LC computed by 6 complex squarings (LC=64) — avoids sin(t*theta) blowup.
// ---------------------------------------------------------------------------
__global__ void __launch_bounds__(1024) scan_carry(const float* __restrict__ Arot,
                                                   const float* __restrict__ x0,
                                                   float* __restrict__ tail,
                                                   int write_tail)
{
    const int tid = threadIdx.x;           // 0..1023
    const int b = tid >> 7, k = tid & 127;

    float Wr = Arot[k * 4 + 0];
    float Wi = Arot[k * 4 + 1];
    #pragma unroll
    for (int i = 0; i < 6; ++i) {          // w -> w^2 -> ... -> w^64
        float nr = Wr * Wr - Wi * Wi;
        float ni = 2.f * Wr * Wi;
        Wr = nr; Wi = ni;
    }

    float2 z = ((const float2*)x0)[b * KHALF + k];
    float zr = z.x, zi = z.y;
    for (int c = 0; c < CPB; ++c) {
        const int cid = b * CPB + c;
        ((float2*)g_in)[cid * KHALF + k] = make_float2(zr, zi);
        float2 s = ((const float2*)g_s)[cid * KHALF + k];
        float nr = fmaf(zr, Wr, fmaf(-zi, Wi, s.x));
        float ni = fmaf(zr, Wi, fmaf( zi, Wr, s.y));
        zr = nr; zi = ni;
    }
    if (write_tail)
        ((float2*)tail)[b * KHALF + k] = make_float2(zr, zi);
}

// ---------------------------------------------------------------------------
// Scan phase C: replay each chunk with the correct incoming state, write x.
// ---------------------------------------------------------------------------
__global__ void __launch_bounds__(128) scan_apply(const float* __restrict__ Arot)
{
    const int cid = blockIdx.x;
    const int k = threadIdx.x;
    const float wc = Arot[k * 4 + 0];
    const float ws = Arot[k * 4 + 1];
    const float2* p = (const float2*)(g_x1 + (size_t)cid * LC * NST) + k;
    float2*       q = (float2*)      (g_x  + (size_t)cid * LC * NST) + k;

    float2 z0 = ((const float2*)g_in)[cid * KHALF + k];
    float zr = z0.x, zi = z0.y;
    #pragma unroll 8
    for (int tt = 0; tt < LC; ++tt) {
        float2 v = p[(size_t)tt * (NST / 2)];
        float nr = fmaf(zr, wc, fmaf(-zi, ws, v.x));
        float ni = fmaf(zr, ws, fmaf( zi, wc, v.y));
        zr = nr; zi = ni;
        q[(size_t)tt * (NST / 2)] = make_float2(zr, zi);
    }
}

// ---------------------------------------------------------------------------
// Launch: gemm1 -> scan A -> scan B -> scan C -> gemm2
// Output: y (8*4096*256 f32) then new_state (8*128*2 f32), concatenated.
// ---------------------------------------------------------------------------
extern "C" void kernel_launch(void* const* d_in, const int* in_sizes, int n_in,
                              void* d_out, int out_size)
{
    const float* u  = (const float*)d_in[0];
    const float* x0 = (const float*)d_in[1];
    const float* A  = (const float*)d_in[2];
    const float* B  = (const float*)d_in[3];
    const float* C  = (const float*)d_in[4];
    float* out = (float*)d_out;

    const int YSZ = ROWS * NST;                       // 8388608
    const int TSZ = BATCH * KHALF * 2;                // 2048
    const int wt = (out_size >= YSZ + TSZ) ? 1 : 0;
    float* tail = out + YSZ;

    gemm_k<0><<<ROWS / 64, 128>>>(u, B, out);         // x1 = u @ B   (writes g_x1)
    scan_local<<<CHUNKS, 128>>>(A);                   // per-chunk local scans
    scan_carry<<<1, 1024>>>(A, x0, tail, wt);         // carries + new_state
    scan_apply<<<CHUNKS, 128>>>(A);                   // x (writes g_x)
    gemm_k<1><<<ROWS / 64, 128>>>(u, C, out);         // y = x @ C    (reads g_x)
}

// round 13
// speedup vs baseline: 1.2062x; 1.2055x over previous
#include <cuda_runtime.h>
#include <cstdint>

// Problem constants (fixed by setup_inputs)
#define BATCH   8
#define LEN     4096
#define ROWS    (BATCH * LEN)      // 32768
#define NST     256                // state/input/output size
#define KHALF   128                // number of 2x2 complex channels
#define LC      64                 // scan chunk length == GEMM block M tile
#define CHUNKS  (ROWS / LC)        // 512
#define CPB     (LEN / LC)         // 64 chunks per batch sequence

// Scratch (device globals: no allocation allowed)
__device__ float g_x1[ROWS * NST];     // u @ B
__device__ float g_s [CHUNKS * NST];   // per-chunk local scan results
__device__ float g_in[CHUNKS * NST];   // per-chunk incoming states

// ---------------------------------------------------------------------------
// helpers
// ---------------------------------------------------------------------------
__device__ __forceinline__ uint32_t f2tf(float f) {
    uint32_t r;
    asm("cvt.rna.tf32.f32 %0, %1;" : "=r"(r) : "f"(f));
    return r;
}

__device__ __forceinline__ void mma_tf32(float* d, const uint32_t* a, const uint32_t* b) {
    asm volatile(
        "mma.sync.aligned.m16n8k8.row.col.f32.tf32.tf32.f32 "
        "{%0,%1,%2,%3}, {%4,%5,%6,%7}, {%8,%9}, {%0,%1,%2,%3};\n"
        : "+f"(d[0]), "+f"(d[1]), "+f"(d[2]), "+f"(d[3])
        : "r"(a[0]), "r"(a[1]), "r"(a[2]), "r"(a[3]), "r"(b[0]), "r"(b[1]));
}

__device__ __forceinline__ void cp16(uint32_t smem, const void* gmem) {
    asm volatile("cp.async.ca.shared.global [%0], [%1], 16;\n" :: "r"(smem), "l"(gmem));
}

// ===========================================================================
// K1: gemm1 (x1 = u @ B) fused with per-chunk zero-init local scan -> g_s.
// Block tile 64x256, BK=16, 4 warps. Dynamic SMEM: As/Bs double buffers,
// aliased after the mainloop by a 64x258 staging tile for the scan.
// SMEM bytes = max(44032, 66048) = 66048.
// ===========================================================================
__global__ void __launch_bounds__(128) gemm_scan1(const float* __restrict__ u,
                                                  const float* __restrict__ Bw,
                                                  const float* __restrict__ Arot)
{
    extern __shared__ float sm1[];
    float (*As)[64][20]  = (float(*)[64][20])sm1;              // [2][64][20]
    float (*Bs)[16][264] = (float(*)[16][264])(sm1 + 2*64*20); // [2][16][264]
    float (*xs)[258]     = (float(*)[258])sm1;                 // alias (post-mainloop)

    const int tid  = threadIdx.x;
    const int warp = tid >> 5;
    const int lane = tid & 31;
    const int g = lane >> 2, t = lane & 3;
    const long mbase = (long)blockIdx.x * 64;

    auto loadTile = [&](int k0, int buf) {
        #pragma unroll
        for (int p = 0; p < 2; ++p) {
            int ch = tid + p * 128;
            int r = ch >> 2, c4 = (ch & 3) * 4;
            cp16((uint32_t)__cvta_generic_to_shared(&As[buf][r][c4]),
                 u + (mbase + r) * NST + k0 + c4);
        }
        #pragma unroll
        for (int p = 0; p < 8; ++p) {
            int ch = tid + p * 128;
            int r = ch >> 6, c = (ch & 63) * 4;
            cp16((uint32_t)__cvta_generic_to_shared(&Bs[buf][r][c]),
                 Bw + (k0 + r) * NST + c);
        }
        asm volatile("cp.async.commit_group;\n");
    };

    float acc[4][8][4];
    #pragma unroll
    for (int i = 0; i < 4; ++i)
        #pragma unroll
        for (int j = 0; j < 8; ++j)
            #pragma unroll
            for (int q = 0; q < 4; ++q) acc[i][j][q] = 0.f;

    loadTile(0, 0);

    for (int it = 0; it < 16; ++it) {
        if (it + 1 < 16) {
            loadTile((it + 1) * 16, (it + 1) & 1);
            asm volatile("cp.async.wait_group 1;\n");
        } else {
            asm volatile("cp.async.wait_group 0;\n");
        }
        __syncthreads();

        const int buf = it & 1;
        const int nb0 = warp * 64;
        #pragma unroll
        for (int kk = 0; kk < 16; kk += 8) {
            uint32_t af[4][4], bf[8][2];
            #pragma unroll
            for (int i = 0; i < 4; ++i) {
                af[i][0] = f2tf(As[buf][i * 16 + g    ][kk + t    ]);
                af[i][1] = f2tf(As[buf][i * 16 + g + 8][kk + t    ]);
                af[i][2] = f2tf(As[buf][i * 16 + g    ][kk + t + 4]);
                af[i][3] = f2tf(As[buf][i * 16 + g + 8][kk + t + 4]);
            }
            #pragma unroll
            for (int j = 0; j < 8; ++j) {
                bf[j][0] = f2tf(Bs[buf][kk + t    ][nb0 + j * 8 + g]);
                bf[j][1] = f2tf(Bs[buf][kk + t + 4][nb0 + j * 8 + g]);
            }
            #pragma unroll
            for (int i = 0; i < 4; ++i)
                #pragma unroll
                for (int j = 0; j < 8; ++j)
                    mma_tf32(acc[i][j], af[i], bf[j]);
        }
        __syncthreads();
    }

    // Epilogue: write x1 tile to gmem AND into xs (aliases dead As/Bs).
    #pragma unroll
    for (int i = 0; i < 4; ++i) {
        long r0 = mbase + i * 16 + g;
        int lr = i * 16 + g;
        #pragma unroll
        for (int j = 0; j < 8; ++j) {
            int cn = warp * 64 + j * 8 + 2 * t;
            float2 v0 = make_float2(acc[i][j][0], acc[i][j][1]);
            float2 v1 = make_float2(acc[i][j][2], acc[i][j][3]);
            *(float2*)&g_x1[r0 * NST + cn]       = v0;
            *(float2*)&g_x1[(r0 + 8) * NST + cn] = v1;
            *(float2*)&xs[lr][cn]     = v0;
            *(float2*)&xs[lr + 8][cn] = v1;
        }
    }
    __syncthreads();

    // Local scan (zero init) over the chunk: thread k handles channel k.
    {
        const int k = tid;   // 0..127
        const float wc = Arot[k * 4 + 0];
        const float ws = Arot[k * 4 + 1];
        float zr = 0.f, zi = 0.f;
        #pragma unroll 8
        for (int tt = 0; tt < LC; ++tt) {
            float2 v = *(const float2*)&xs[tt][2 * k];
            float nr = fmaf(zr, wc, fmaf(-zi, ws, v.x));
            float ni = fmaf(zr, ws, fmaf( zi, wc, v.y));
            zr = nr; zi = ni;
        }
        ((float2*)g_s)[blockIdx.x * KHALF + k] = make_float2(zr, zi);
    }
}

// ===========================================================================
// K2: carry propagation, one block per batch. Stage the batch's chunk sums
// (64 chunks x 256 floats = 64KB) in SMEM so the serial chain hits LDS.
//   in_0 = x0;  in_{c+1} = in_c * w^64 + s_c;  new_state = in_{CPB}
// ===========================================================================
__global__ void __launch_bounds__(128) scan_carry(const float* __restrict__ Arot,
                                                  const float* __restrict__ x0,
                                                  float* __restrict__ tail,
                                                  int write_tail)
{
    extern __shared__ float ss[];               // [64][256]
    const int b = blockIdx.x;
    const int k = threadIdx.x;                  // 0..127

    const float4* src = (const float4*)(g_s + (size_t)b * CPB * NST);
    float4* dst = (float4*)ss;
    #pragma unroll
    for (int i = 0; i < 32; ++i)
        dst[k + i * 128] = src[k + i * 128];
    __syncthreads();

    float Wr = Arot[k * 4 + 0];
    float Wi = Arot[k * 4 + 1];
    #pragma unroll
    for (int i = 0; i < 6; ++i) {               // w -> w^64 by squaring
        float nr = Wr * Wr - Wi * Wi;
        float ni = 2.f * Wr * Wi;
        Wr = nr; Wi = ni;
    }

    float2 z = ((const float2*)x0)[b * KHALF + k];
    float zr = z.x, zi = z.y;
    #pragma unroll 8
    for (int c = 0; c < CPB; ++c) {
        ((float2*)g_in)[(b * CPB + c) * KHALF + k] = make_float2(zr, zi);
        float2 s = ((const float2*)ss)[c * KHALF + k];
        float nr = fmaf(zr, Wr, fmaf(-zi, Wi, s.x));
        float ni = fmaf(zr, Wi, fmaf( zi, Wr, s.y));
        zr = nr; zi = ni;
    }
    if (write_tail)
        ((float2*)tail)[b * KHALF + k] = make_float2(zr, zi);
}

// ===========================================================================
// K3: fused apply-scan + gemm2 (y = x @ C).
// Prologue: thread k streams the chunk's x1 column pair from gmem (8-deep
// load batching for MLP), applies the recurrence from g_in, writes x into
// SMEM xs[64][260]. Mainloop reads A fragments straight from xs (stride 260
// -> bank = 4g+t = lane, conflict-free); only C is cp.async double-buffered.
// SMEM bytes = 64*260*4 + 2*16*264*4 = 66560 + 33792 = 100352.
// ===========================================================================
__global__ void __launch_bounds__(128) gemm_scan2(const float* __restrict__ Cw,
                                                  const float* __restrict__ Arot,
                                                  float* __restrict__ y)
{
    extern __shared__ float sm3[];
    float (*xs)[260]     = (float(*)[260])sm3;                 // 64 x 260
    float (*Bs)[16][264] = (float(*)[16][264])(sm3 + 64*260);  // [2][16][264]

    const int tid  = threadIdx.x;
    const int warp = tid >> 5;
    const int lane = tid & 31;
    const int g = lane >> 2, t = lane & 3;
    const int cid = blockIdx.x;
    const long mbase = (long)cid * 64;

    auto loadB = [&](int k0, int buf) {
        #pragma unroll
        for (int p = 0; p < 8; ++p) {
            int ch = tid + p * 128;
            int r = ch >> 6, c = (ch & 63) * 4;
            cp16((uint32_t)__cvta_generic_to_shared(&Bs[buf][r][c]),
                 Cw + (k0 + r) * NST + c);
        }
        asm volatile("cp.async.commit_group;\n");
    };

    loadB(0, 0);   // overlap first C tile with the scan below

    // ---- apply-scan: gmem x1 -> recurrence -> xs ----
    {
        const int k = tid;
        const float wc = Arot[k * 4 + 0];
        const float ws = Arot[k * 4 + 1];
        const float2* p = (const float2*)(g_x1 + (size_t)cid * LC * NST) + k;
        float2 z0 = ((const float2*)g_in)[cid * KHALF + k];
        float zr = z0.x, zi = z0.y;
        #pragma unroll
        for (int tt0 = 0; tt0 < LC; tt0 += 8) {
            float2 v[8];
            #pragma unroll
            for (int j = 0; j < 8; ++j)
                v[j] = p[(size_t)(tt0 + j) * (NST / 2)];
            #pragma unroll
            for (int j = 0; j < 8; ++j) {
                float nr = fmaf(zr, wc, fmaf(-zi, ws, v[j].x));
                float ni = fmaf(zr, ws, fmaf( zi, wc, v[j].y));
                zr = nr; zi = ni;
                *(float2*)&xs[tt0 + j][2 * k] = make_float2(zr, zi);
            }
        }
    }
    __syncthreads();

    // ---- mainloop: y_tile = xs @ C ----
    float acc[4][8][4];
    #pragma unroll
    for (int i = 0; i < 4; ++i)
        #pragma unroll
        for (int j = 0; j < 8; ++j)
            #pragma unroll
            for (int q = 0; q < 4; ++q) acc[i][j][q] = 0.f;

    for (int it = 0; it < 16; ++it) {
        if (it + 1 < 16) {
            loadB((it + 1) * 16, (it + 1) & 1);
            asm volatile("cp.async.wait_group 1;\n");
        } else {
            asm volatile("cp.async.wait_group 0;\n");
        }
        __syncthreads();

        const int buf = it & 1;
        const int k0  = it * 16;
        const int nb0 = warp * 64;
        #pragma unroll
        for (int kk = 0; kk < 16; kk += 8) {
            uint32_t af[4][4], bf[8][2];
            #pragma unroll
            for (int i = 0; i < 4; ++i) {
                af[i][0] = f2tf(xs[i * 16 + g    ][k0 + kk + t    ]);
                af[i][1] = f2tf(xs[i * 16 + g + 8][k0 + kk + t    ]);
                af[i][2] = f2tf(xs[i * 16 + g    ][k0 + kk + t + 4]);
                af[i][3] = f2tf(xs[i * 16 + g + 8][k0 + kk + t + 4]);
            }
            #pragma unroll
            for (int j = 0; j < 8; ++j) {
                bf[j][0] = f2tf(Bs[buf][kk + t    ][nb0 + j * 8 + g]);
                bf[j][1] = f2tf(Bs[buf][kk + t + 4][nb0 + j * 8 + g]);
            }
            #pragma unroll
            for (int i = 0; i < 4; ++i)
                #pragma unroll
                for (int j = 0; j < 8; ++j)
                    mma_tf32(acc[i][j], af[i], bf[j]);
        }
        __syncthreads();
    }

    #pragma unroll
    for (int i = 0; i < 4; ++i) {
        long r0 = mbase + i * 16 + g;
        #pragma unroll
        for (int j = 0; j < 8; ++j) {
            int cn = warp * 64 + j * 8 + 2 * t;
            *(float2*)&y[r0 * NST + cn]       = make_float2(acc[i][j][0], acc[i][j][1]);
            *(float2*)&y[(r0 + 8) * NST + cn] = make_float2(acc[i][j][2], acc[i][j][3]);
        }
    }
}

// ---------------------------------------------------------------------------
// Launch: K1 -> K2 -> K3.
// Output: y (8*4096*256 f32) then new_state (8*128*2 f32), concatenated.
// ---------------------------------------------------------------------------
extern "C" void kernel_launch(void* const* d_in, const int* in_sizes, int n_in,
                              void* d_out, int out_size)
{
    const float* u  = (const float*)d_in[0];
    const float* x0 = (const float*)d_in[1];
    const float* A  = (const float*)d_in[2];
    const float* B  = (const float*)d_in[3];
    const float* C  = (const float*)d_in[4];
    float* out = (float*)d_out;

    const int YSZ = ROWS * NST;
    const int TSZ = BATCH * KHALF * 2;
    const int wt = (out_size >= YSZ + TSZ) ? 1 : 0;
    float* tail = out + YSZ;

    const int SM1 = 66048;     // max(As+Bs, xs[64][258])
    const int SM2 = 65536;     // ss[64][256]
    const int SM3 = 100352;    // xs[64][260] + Bs

    cudaFuncSetAttribute(gemm_scan1, cudaFuncAttributeMaxDynamicSharedMemorySize, SM1);
    cudaFuncSetAttribute(scan_carry, cudaFuncAttributeMaxDynamicSharedMemorySize, SM2);
    cudaFuncSetAttribute(gemm_scan2, cudaFuncAttributeMaxDynamicSharedMemorySize, SM3);

    gemm_scan1<<<CHUNKS, 128, SM1>>>(u, B, A);           // x1 + chunk sums
    scan_carry<<<BATCH, 128, SM2>>>(A, x0, tail, wt);    // carries + new_state
    gemm_scan2<<<CHUNKS, 128, SM3>>>(C, A, out);         // x (in SMEM) @ C -> y
}